// round 11
// baseline (speedup 1.0000x reference)
#include <cuda_runtime.h>
#include <math_constants.h>

// MultiSimilarityLoss: sim_mat [8192,8192] f32, labels [8192] i64-or-i32 -> scalar f32
//
// R11: single persistent kernel, cp.async double-buffered row staging.
//  - 304 CTAs x 512 thr (2/SM, 32 warps/SM). Each CTA loops ~27 rows.
//  - Next row streamed into the other 32 KB smem buffer via cp.async.cg
//    (L1-bypass) while current row is reduced/exp'd -> load/compute overlap
//    without register pressure (R10's failure mode).
//  - Column labels u16-packed in 8 regs, loaded ONCE per CTA from the raw
//    labels buffer (dtype auto-detected) -> no prep kernel, ~20 MB label traffic.
//  - Poison: same-labeled x = s-4; min over all x == hardest positive,
//    max over all x == hardest negative. Dense pass2: FFMA+MUFU.EX2+FSETP+@FADD.
//  - Fused last-CTA deterministic reduction (graph-replay safe counter).

constexpr int BN    = 8192;
constexpr int NT    = 512;
constexpr int NSLOT = BN / 4 / NT;   // 4 float4 slots per thread per row
constexpr int NWARP = NT / 32;       // 16
constexpr int GRID  = 152 * 2;       // persistent CTAs (GB300: 152 SMs)

constexpr float ONE_MEPS = 1.0f - 1e-5f;
constexpr float POISON   = 4.0f;
constexpr float PB       = ONE_MEPS - POISON;     // ~ -3.00001
constexpr float K40 = 57.706801635558536f;        //  40*log2(e)
constexpr float C40 = -28.853400817779268f;       // -20*log2(e)
constexpr float KP  = -2.885390081777927f;        //  -2*log2(e)
constexpr float CP  = -10.098865286222744f;       //  -7*log2(e)

__device__ float g_row_loss[BN];
__device__ int   g_done = 0;

__device__ __forceinline__ float ex2(float a) {
    float r;
    asm("ex2.approx.ftz.f32 %0, %1;" : "=f"(r) : "f"(a));
    return r;
}

__device__ __forceinline__ void cpasync16(float4* dst_smem, const float4* src) {
    unsigned s = (unsigned)__cvta_generic_to_shared(dst_smem);
    asm volatile("cp.async.cg.shared.global [%0], [%1], 16;" :: "r"(s), "l"(src));
}
__device__ __forceinline__ void cp_commit() {
    asm volatile("cp.async.commit_group;");
}
__device__ __forceinline__ void cp_wait0() {
    asm volatile("cp.async.wait_group 0;");
}
__device__ __forceinline__ void cp_wait1() {
    asm volatile("cp.async.wait_group 1;");
}

extern __shared__ float4 dynbuf[];   // 2 x 2048 float4 = 64 KB

__global__ __launch_bounds__(NT, 2) void ms_kernel(
    const float* __restrict__ sim, const void* __restrict__ labels_raw,
    float* __restrict__ out)
{
    const int tid  = threadIdx.x;
    const int lane = tid & 31;
    const int warp = tid >> 5;

    float4* buf[2] = { dynbuf, dynbuf + (BN / 4) };

    __shared__ float s_mn[NWARP], s_mx[NWARP];
    __shared__ float s_minall, s_maxneg;
    __shared__ float s_ps[NWARP], s_ns[NWARP];
    __shared__ int   s_last;

    // ---- dtype detection (per-warp ballot, uniform result) ----
    // int64 labels < 1024 => every odd 32-bit word zero. 32 sampled words:
    // P(false positive for int32) ~ (1/1024)^32 ~ 0.
    const unsigned* wraw = (const unsigned*)labels_raw;
    unsigned fw = __ldg(&wraw[2 * lane + 1]);
    const bool is64 = (__ballot_sync(0xffffffffu, fw != 0u) == 0u);

    // ---- column labels for this thread's 16 columns, u16-packed, ONCE ----
    uint2 lab[NSLOT];
    #pragma unroll
    for (int k = 0; k < NSLOT; k++) {
        int j = tid + k * NT;                 // float4 slot -> cols 4j..4j+3
        unsigned l0, l1, l2, l3;
        if (is64) {
            longlong2 p0 = __ldg((const longlong2*)labels_raw + 2 * j);
            longlong2 p1 = __ldg((const longlong2*)labels_raw + 2 * j + 1);
            l0 = (unsigned)p0.x; l1 = (unsigned)p0.y;
            l2 = (unsigned)p1.x; l3 = (unsigned)p1.y;
        } else {
            int4 p = __ldg((const int4*)labels_raw + j);
            l0 = p.x; l1 = p.y; l2 = p.z; l3 = p.w;
        }
        lab[k].x = (l0 & 0xFFFFu) | (l1 << 16);
        lab[k].y = (l2 & 0xFFFFu) | (l3 << 16);
    }

    // ---- initial prefetch ----
    int row = blockIdx.x;
    {
        const float4* srow = (const float4*)(sim + (size_t)row * BN);
        #pragma unroll
        for (int k = 0; k < NSLOT; k++) cpasync16(&buf[0][tid + k * NT], srow + tid + k * NT);
        cp_commit();
    }
    unsigned ml_cur = is64 ? (unsigned)(((const long long*)labels_raw)[row]) & 0xFFFFu
                           : ((const unsigned*)labels_raw)[row] & 0xFFFFu;
    int c = 0;

    const float pb_up = __int_as_float(__float_as_int(PB) - 1);  // next float toward 0

    for (;;) {
        const int  next = row + GRID;
        const bool hn   = next < BN;

        // issue next row's async copy into the other buffer
        if (hn) {
            const float4* srow = (const float4*)(sim + (size_t)next * BN);
            #pragma unroll
            for (int k = 0; k < NSLOT; k++) cpasync16(&buf[1 - c][tid + k * NT], srow + tid + k * NT);
            cp_commit();
            cp_wait1();              // current buffer's group done; next may fly
        } else {
            cp_wait0();
        }
        __syncthreads();

        const float4* B = buf[c];
        const unsigned pat = ml_cur * 0x00010001u;   // row label in both u16 halves

        // ---- pass 1: poison + min/max over x ----
        float mn = CUDART_INF_F;    // min over all x == hardest positive (poisoned)
        float mx = -CUDART_INF_F;   // max over all x == hardest negative
        #pragma unroll
        for (int k = 0; k < NSLOT; k++) {
            float4 x = B[tid + k * NT];
            unsigned q0 = lab[k].x ^ pat;
            unsigned q1 = lab[k].y ^ pat;
            float x0 = x.x; if ((q0 & 0xFFFFu) == 0u) x0 -= POISON;   // even: low half
            float x1 = x.y; if (q0 < 0x10000u)        x1 -= POISON;   // odd: high half
            float x2 = x.z; if ((q1 & 0xFFFFu) == 0u) x2 -= POISON;
            float x3 = x.w; if (q1 < 0x10000u)        x3 -= POISON;
            mn = fminf(fminf(mn, fminf(x0, x1)), fminf(x2, x3));
            mx = fmaxf(fmaxf(mx, fmaxf(x0, x1)), fmaxf(x2, x3));
        }
        const float my_mn = mn;

        // fetch next row's label early (hides its latency behind the reduce)
        if (hn) ml_cur = is64 ? (unsigned)(((const long long*)labels_raw)[next]) & 0xFFFFu
                              : ((const unsigned*)labels_raw)[next] & 0xFFFFu;

        // ---- block reduce min_all / max_neg ----
        #pragma unroll
        for (int o = 16; o; o >>= 1) {
            mn = fminf(mn, __shfl_xor_sync(0xffffffffu, mn, o));
            mx = fmaxf(mx, __shfl_xor_sync(0xffffffffu, mx, o));
        }
        if (lane == 0) { s_mn[warp] = mn; s_mx[warp] = mx; }
        __syncthreads();
        if (warp == 0) {
            float aa = (lane < NWARP) ? s_mn[lane] : CUDART_INF_F;
            float bb = (lane < NWARP) ? s_mx[lane] : -CUDART_INF_F;
            #pragma unroll
            for (int o = 8; o; o >>= 1) {
                aa = fminf(aa, __shfl_xor_sync(0xffffffffu, aa, o));
                bb = fmaxf(bb, __shfl_xor_sync(0xffffffffu, bb, o));
            }
            if (lane == 0) { s_minall = aa; s_maxneg = bb; }
        }
        __syncthreads();

        const float min_all = s_minall;
        const float tn = (min_all < pb_up) ? (min_all + 3.9f) : CUDART_INF_F;

        // ---- dense neg pass: re-read B, recompute poison (labels in regs) ----
        float ns0 = 0.0f, ns1 = 0.0f, ns2 = 0.0f, ns3 = 0.0f;
        #pragma unroll
        for (int k = 0; k < NSLOT; k++) {
            float4 x = B[tid + k * NT];
            unsigned q0 = lab[k].x ^ pat;
            unsigned q1 = lab[k].y ^ pat;
            float x0 = x.x; if ((q0 & 0xFFFFu) == 0u) x0 -= POISON;
            float x1 = x.y; if (q0 < 0x10000u)        x1 -= POISON;
            float x2 = x.z; if ((q1 & 0xFFFFu) == 0u) x2 -= POISON;
            float x3 = x.w; if (q1 < 0x10000u)        x3 -= POISON;
            float e0 = ex2(fmaf(x0, K40, C40));
            float e1 = ex2(fmaf(x1, K40, C40));
            float e2 = ex2(fmaf(x2, K40, C40));
            float e3 = ex2(fmaf(x3, K40, C40));
            if (x0 > tn) ns0 += e0;    // poisoned x <= -3 < tn always (tn >= -1.1)
            if (x1 > tn) ns1 += e1;
            if (x2 > tn) ns2 += e2;
            if (x3 > tn) ns3 += e3;
        }
        float neg_sum = (ns0 + ns1) + (ns2 + ns3);

        // ---- rare pos pass ----
        float pos_sum = 0.0f;
        if (my_mn < pb_up) {
            float tp = fminf(pb_up, s_maxneg - 3.9f);
            #pragma unroll
            for (int k = 0; k < NSLOT; k++) {
                float4 x = B[tid + k * NT];
                unsigned q0 = lab[k].x ^ pat;
                unsigned q1 = lab[k].y ^ pat;
                float x0 = x.x; if ((q0 & 0xFFFFu) == 0u) x0 -= POISON;
                float x1 = x.y; if (q0 < 0x10000u)        x1 -= POISON;
                float x2 = x.z; if ((q1 & 0xFFFFu) == 0u) x2 -= POISON;
                float x3 = x.w; if (q1 < 0x10000u)        x3 -= POISON;
                float e0 = ex2(fmaf(x0, KP, CP));   // exp(-2(s-0.5)) on poisoned x
                float e1 = ex2(fmaf(x1, KP, CP));
                float e2 = ex2(fmaf(x2, KP, CP));
                float e3 = ex2(fmaf(x3, KP, CP));
                if (x0 < tp) pos_sum += e0;
                if (x1 < tp) pos_sum += e1;
                if (x2 < tp) pos_sum += e2;
                if (x3 < tp) pos_sum += e3;
            }
        }

        // ---- block reduce the two sums, write row loss ----
        #pragma unroll
        for (int o = 16; o; o >>= 1) {
            pos_sum += __shfl_xor_sync(0xffffffffu, pos_sum, o);
            neg_sum += __shfl_xor_sync(0xffffffffu, neg_sum, o);
        }
        if (lane == 0) { s_ps[warp] = pos_sum; s_ns[warp] = neg_sum; }
        __syncthreads();        // all reads of B done -> next iter may overwrite it
        if (tid == 0) {
            float ps = 0.0f, ns = 0.0f;
            #pragma unroll
            for (int wi = 0; wi < NWARP; wi++) { ps += s_ps[wi]; ns += s_ns[wi]; }
            float loss = 0.0f;
            if (ps > 0.0f && ns > 0.0f)      // exp > 0: ps>0 <=> any(sel_pos)
                loss = log1pf(ps) * 0.5f + log1pf(ns) * 0.025f;
            g_row_loss[row] = loss;
        }

        if (!hn) break;
        row = next;
        c ^= 1;
    }

    // ---- CTA completion counter; last CTA reduces deterministically ----
    __syncthreads();
    if (tid == 0) {
        __threadfence();
        int old = atomicAdd(&g_done, 1);
        s_last = (old == GRID - 1) ? 1 : 0;
    }
    __syncthreads();

    if (s_last) {
        __threadfence();              // acquire: see all rows' losses
        float sum = 0.0f;
        #pragma unroll
        for (int i = 0; i < BN / NT; i++) sum += g_row_loss[tid + i * NT];
        #pragma unroll
        for (int o = 16; o; o >>= 1) sum += __shfl_xor_sync(0xffffffffu, sum, o);
        if (lane == 0) s_ps[warp] = sum;
        __syncthreads();
        if (tid == 0) {
            float t = 0.0f;
            #pragma unroll
            for (int wi = 0; wi < NWARP; wi++) t += s_ps[wi];
            out[0] = t / (float)BN;
            g_done = 0;               // reset for next graph replay
        }
    }
}

extern "C" void kernel_launch(void* const* d_in, const int* in_sizes, int n_in,
                              void* d_out, int out_size) {
    // Guard against input ordering: sim has BN*BN elements, labels BN.
    const void* p0 = d_in[0];
    const void* p1 = d_in[1];
    const float* sim;
    const void*  labels;
    if (in_sizes[0] == BN) { labels = p0; sim = (const float*)p1; }
    else                   { sim = (const float*)p0; labels = p1; }
    float* out = (float*)d_out;

    static bool attr_set = false;
    if (!attr_set) {
        cudaFuncSetAttribute(ms_kernel, cudaFuncAttributeMaxDynamicSharedMemorySize,
                             2 * (BN / 4) * (int)sizeof(float4));
        attr_set = true;
    }
    ms_kernel<<<GRID, NT, 2 * (BN / 4) * sizeof(float4)>>>(sim, labels, out);
}

// round 12
// speedup vs baseline: 1.2040x; 1.2040x over previous
#include <cuda_runtime.h>
#include <math_constants.h>

// MultiSimilarityLoss: sim_mat [8192,8192] f32, labels [8192] i64-or-i32 -> scalar f32
//
// R12 = R6's row kernel bit-exact (the empirical optimum across R4-R11:
// 256thr x 32 elems; 2 chunks x 4 front-batched LDG.cs.128; int32 L1-resident
// labels via prep kernel; 32 KB smem poisoned-value buffer; 5 CTAs/SM)
// + fused last-CTA final reduction (eliminates the separate reduce kernel).
//
//  - Poison: same-labeled elements x = s - 4 (in [-5,-3]).
//    * min over ALL x == hardest positive (self always poisoned, negs >= -1).
//    * max over ALL x == hardest negative (poison can't win).
//  - Dense pass2: LDS.128 + 4x(FFMA + MUFU.EX2 + FSETP + @FADD).
//  - Pos-side exp in a rare branch (~1.5% of threads).

constexpr int BN        = 8192;
constexpr int NTHREADS  = 256;
constexpr int PER       = BN / NTHREADS;   // 32
constexpr int NVEC      = PER / 4;         // 8 float4 slots per thread
constexpr int NWARPS    = NTHREADS / 32;   // 8

constexpr float ONE_MEPS = 1.0f - 1e-5f;          // pos threshold on s
constexpr float POISON   = 4.0f;
constexpr float PB       = ONE_MEPS - POISON;     // poisoned pos boundary ~ -3.00001
// exp(40(s-0.5)) = exp2(x*K40 + C40)
constexpr float K40 = 57.706801635558536f;        //  40*log2(e)
constexpr float C40 = -28.853400817779268f;       // -20*log2(e)
// exp(-2(s-0.5)) with s = x+4  ->  exp2(x*KP + CP)
constexpr float KP  = -2.885390081777927f;        //  -2*log2(e)
constexpr float CP  = -10.098865286222744f;       //  -7*log2(e)

__device__ int   g_labels[BN];
__device__ float g_row_loss[BN];
__device__ int   g_done = 0;

__device__ __forceinline__ float ex2(float a) {
    float r;
    asm("ex2.approx.ftz.f32 %0, %1;" : "=f"(r) : "f"(a));
    return r;
}

// Streaming (evict-first) 128-bit load: touched exactly once.
__device__ __forceinline__ float4 ldcs4(const float4* p) {
    float4 r;
    asm("ld.global.cs.v4.f32 {%0,%1,%2,%3}, [%4];"
        : "=f"(r.x), "=f"(r.y), "=f"(r.z), "=f"(r.w) : "l"(p));
    return r;
}

// Dtype detection: odd 32-bit words are high halves (all zero, labels<1024) iff
// int64. 32 sampled words: P(false positive for int32) = (1/1024)^32 ~ 0.
__global__ __launch_bounds__(512) void prep_labels_kernel(const void* __restrict__ labels_raw) {
    const int tid = threadIdx.x;
    const unsigned* w = (const unsigned*)labels_raw;

    __shared__ int s_is64;
    if (tid < 32) {
        unsigned f = w[2 * tid + 1];
        unsigned any = __ballot_sync(0xffffffffu, f != 0u);
        if (tid == 0) s_is64 = (any == 0u) ? 1 : 0;
    }
    __syncthreads();

    int start = blockIdx.x * 512 + tid;
    if (s_is64) {
        const long long* l64 = (const long long*)labels_raw;
        for (int i = start; i < BN; i += 512 * 16) g_labels[i] = (int)l64[i];
    } else {
        const int* l32 = (const int*)labels_raw;
        for (int i = start; i < BN; i += 512 * 16) g_labels[i] = l32[i];
    }
}

__global__ __launch_bounds__(NTHREADS, 5) void row_kernel(
    const float* __restrict__ sim, float* __restrict__ out)
{
    const int row  = blockIdx.x;
    const int tid  = threadIdx.x;
    const int lane = tid & 31;
    const int warp = tid >> 5;
    const int my_label = __ldg(&g_labels[row]);

    __shared__ float4 vsm[NVEC * NTHREADS];            // 32 KB poisoned values
    __shared__ float s_mn[NWARPS], s_mx[NWARPS];
    __shared__ float s_minall, s_maxneg;
    __shared__ float s_ps[NWARPS], s_ns[NWARPS];
    __shared__ int   s_last;

    const float4* __restrict__ srow4 = reinterpret_cast<const float4*>(sim + (size_t)row * BN);
    const int4*   __restrict__ lab4  = reinterpret_cast<const int4*>(g_labels);

    // ---- pass 1: 2 chunks of (4 sim float4 + 4 label int4) front-batched ----
    float mn = CUDART_INF_F;    // min over all x == hardest positive (poisoned)
    float mx = -CUDART_INF_F;   // max over all x == hardest negative

    #pragma unroll
    for (int c = 0; c < 2; c++) {
        float4 a[4];
        int4   b[4];
        #pragma unroll
        for (int k = 0; k < 4; k++) a[k] = ldcs4(srow4 + tid + (c * 4 + k) * NTHREADS);
        #pragma unroll
        for (int k = 0; k < 4; k++) b[k] = __ldg(lab4 + tid + (c * 4 + k) * NTHREADS);
        #pragma unroll
        for (int k = 0; k < 4; k++) {
            float sv[4] = {a[k].x, a[k].y, a[k].z, a[k].w};
            int   lv[4] = {b[k].x, b[k].y, b[k].z, b[k].w};
            float xv[4];
            #pragma unroll
            for (int e = 0; e < 4; e++) {
                float x = sv[e];
                if (lv[e] == my_label) x -= POISON;    // ISETP + @FADD
                xv[e] = x;
                mn = fminf(mn, x);                     // FMNMX
                mx = fmaxf(mx, x);                     // FMNMX
            }
            vsm[(c * 4 + k) * NTHREADS + tid] = make_float4(xv[0], xv[1], xv[2], xv[3]);
        }
    }
    const float my_mn = mn;                            // thread-local pos trigger

    // ---- block reduce min_all / max_neg ----
    #pragma unroll
    for (int o = 16; o; o >>= 1) {
        mn = fminf(mn, __shfl_xor_sync(0xffffffffu, mn, o));
        mx = fmaxf(mx, __shfl_xor_sync(0xffffffffu, mx, o));
    }
    if (lane == 0) { s_mn[warp] = mn; s_mx[warp] = mx; }
    __syncthreads();
    if (warp == 0) {
        float a = (lane < NWARPS) ? s_mn[lane] : CUDART_INF_F;
        float b = (lane < NWARPS) ? s_mx[lane] : -CUDART_INF_F;
        #pragma unroll
        for (int o = 4; o; o >>= 1) {
            a = fminf(a, __shfl_xor_sync(0xffffffffu, a, o));
            b = fmaxf(b, __shfl_xor_sync(0xffffffffu, b, o));
        }
        if (lane == 0) { s_minall = a; s_maxneg = b; }
    }
    __syncthreads();

    const float pb_up = __int_as_float(__float_as_int(PB) - 1);  // next float toward 0
    // Positive exists iff min_all < pb_up. Then hardest positive (poisoned) =
    // min_all, and sel_neg threshold tn = min_pos - 0.1 = min_all + 3.9.
    const float min_all = s_minall;
    const float tn = (min_all < pb_up) ? (min_all + 3.9f) : CUDART_INF_F;

    // ---- dense neg pass from smem: LDS.128 + 4x(FFMA+MUFU+FSETP+@FADD) ----
    float ns0 = 0.0f, ns1 = 0.0f, ns2 = 0.0f, ns3 = 0.0f;
    #pragma unroll
    for (int j = 0; j < NVEC; j++) {
        float4 x = vsm[j * NTHREADS + tid];
        float e0 = ex2(fmaf(x.x, K40, C40));
        float e1 = ex2(fmaf(x.y, K40, C40));
        float e2 = ex2(fmaf(x.z, K40, C40));
        float e3 = ex2(fmaf(x.w, K40, C40));
        if (x.x > tn) ns0 += e0;    // poisoned x <= -3 < tn always (tn >= -1.1)
        if (x.y > tn) ns1 += e1;
        if (x.z > tn) ns2 += e2;
        if (x.w > tn) ns3 += e3;
    }
    float neg_sum = (ns0 + ns1) + (ns2 + ns3);

    // ---- rare pos pass (this thread owns >= 1 positive) ----
    float pos_sum = 0.0f;
    if (my_mn < pb_up) {
        // sel_pos: x <= PB (positive) AND s - 0.1 < max_neg i.e. x < max_neg - 3.9
        float tp = fminf(pb_up, s_maxneg - 3.9f);
        #pragma unroll
        for (int j = 0; j < NVEC; j++) {
            float4 x = vsm[j * NTHREADS + tid];
            float e0 = ex2(fmaf(x.x, KP, CP));   // exp(-2(s-0.5)) on poisoned x
            float e1 = ex2(fmaf(x.y, KP, CP));
            float e2 = ex2(fmaf(x.z, KP, CP));
            float e3 = ex2(fmaf(x.w, KP, CP));
            if (x.x < tp) pos_sum += e0;
            if (x.y < tp) pos_sum += e1;
            if (x.z < tp) pos_sum += e2;
            if (x.w < tp) pos_sum += e3;
        }
    }

    // ---- block reduce the two sums, write row loss ----
    #pragma unroll
    for (int o = 16; o; o >>= 1) {
        pos_sum += __shfl_xor_sync(0xffffffffu, pos_sum, o);
        neg_sum += __shfl_xor_sync(0xffffffffu, neg_sum, o);
    }
    if (lane == 0) { s_ps[warp] = pos_sum; s_ns[warp] = neg_sum; }
    __syncthreads();
    if (tid == 0) {
        float ps = 0.0f, ns = 0.0f;
        #pragma unroll
        for (int wi = 0; wi < NWARPS; wi++) { ps += s_ps[wi]; ns += s_ns[wi]; }
        float loss = 0.0f;
        if (ps > 0.0f && ns > 0.0f)      // exp > 0: ps>0 <=> any(sel_pos)
            loss = log1pf(ps) * 0.5f + log1pf(ns) * 0.025f;
        g_row_loss[row] = loss;
        __threadfence();
        int old = atomicAdd(&g_done, 1);
        s_last = (old == BN - 1) ? 1 : 0;
    }
    __syncthreads();

    // ---- last CTA: deterministic final reduction + counter reset ----
    if (s_last) {
        __threadfence();                 // acquire: see all rows' losses
        float sum = 0.0f;
        #pragma unroll
        for (int i = 0; i < BN / NTHREADS; i++) sum += g_row_loss[tid + i * NTHREADS];
        #pragma unroll
        for (int o = 16; o; o >>= 1) sum += __shfl_xor_sync(0xffffffffu, sum, o);
        if (lane == 0) s_ps[warp] = sum;
        __syncthreads();
        if (tid == 0) {
            float t = 0.0f;
            #pragma unroll
            for (int wi = 0; wi < NWARPS; wi++) t += s_ps[wi];
            out[0] = t / (float)BN;
            g_done = 0;                  // reset for next graph replay
        }
    }
}

extern "C" void kernel_launch(void* const* d_in, const int* in_sizes, int n_in,
                              void* d_out, int out_size) {
    // Guard against input ordering: sim has BN*BN elements, labels BN.
    const void* p0 = d_in[0];
    const void* p1 = d_in[1];
    const float* sim;
    const void*  labels;
    if (in_sizes[0] == BN) { labels = p0; sim = (const float*)p1; }
    else                   { sim = (const float*)p0; labels = p1; }
    float* out = (float*)d_out;

    prep_labels_kernel<<<16, 512>>>(labels);
    row_kernel<<<BN, NTHREADS>>>(sim, out);
}

// round 13
// speedup vs baseline: 1.2046x; 1.0005x over previous
#include <cuda_runtime.h>
#include <math_constants.h>

// MultiSimilarityLoss: sim_mat [8192,8192] f32, labels [8192] i64-or-i32 -> scalar f32
//
// R13 = R6 structure exactly (3 kernels: prep -> int32 g_labels; row; reduce.
// 256thr x 32 elems; int32 L1-resident labels; 32 KB smem value buffer;
// 5 CTAs/SM; NO completion-counter atomics -- R12 showed they serialize),
// with ONE change: pass 1 loads issued in 4 non-unrolled chunks of
// (2 sim LDG.cs.128 + 2 label int4) instead of one 8-deep front batch,
// cutting the per-SM L1tex queue depth ~4x to shrink cross-CTA spread.
//
//  - Poison: same-labeled elements x = s - 4 (in [-5,-3]).
//    * min over ALL x == hardest positive (self always poisoned, negs >= -1).
//    * max over ALL x == hardest negative (poison can't win).
//  - Dense pass2: LDS.128 + 4x(FFMA + MUFU.EX2 + FSETP + @FADD).
//  - Pos-side exp in a rare branch (~1.5% of threads).

constexpr int BN        = 8192;
constexpr int NTHREADS  = 256;
constexpr int PER       = BN / NTHREADS;   // 32
constexpr int NVEC      = PER / 4;         // 8 float4 slots per thread
constexpr int NWARPS    = NTHREADS / 32;   // 8

constexpr float ONE_MEPS = 1.0f - 1e-5f;          // pos threshold on s
constexpr float POISON   = 4.0f;
constexpr float PB       = ONE_MEPS - POISON;     // poisoned pos boundary ~ -3.00001
// exp(40(s-0.5)) = exp2(x*K40 + C40)
constexpr float K40 = 57.706801635558536f;        //  40*log2(e)
constexpr float C40 = -28.853400817779268f;       // -20*log2(e)
// exp(-2(s-0.5)) with s = x+4  ->  exp2(x*KP + CP)
constexpr float KP  = -2.885390081777927f;        //  -2*log2(e)
constexpr float CP  = -10.098865286222744f;       //  -7*log2(e)

__device__ int   g_labels[BN];
__device__ float g_row_loss[BN];

__device__ __forceinline__ float ex2(float a) {
    float r;
    asm("ex2.approx.ftz.f32 %0, %1;" : "=f"(r) : "f"(a));
    return r;
}

// Streaming (evict-first) 128-bit load: touched exactly once.
__device__ __forceinline__ float4 ldcs4(const float4* p) {
    float4 r;
    asm("ld.global.cs.v4.f32 {%0,%1,%2,%3}, [%4];"
        : "=f"(r.x), "=f"(r.y), "=f"(r.z), "=f"(r.w) : "l"(p));
    return r;
}

// Dtype detection: odd 32-bit words are high halves (all zero, labels<1024) iff
// int64. 32 sampled words: P(false positive for int32) = (1/1024)^32 ~ 0.
__global__ __launch_bounds__(512) void prep_labels_kernel(const void* __restrict__ labels_raw) {
    const int tid = threadIdx.x;
    const unsigned* w = (const unsigned*)labels_raw;

    __shared__ int s_is64;
    if (tid < 32) {
        unsigned f = w[2 * tid + 1];
        unsigned any = __ballot_sync(0xffffffffu, f != 0u);
        if (tid == 0) s_is64 = (any == 0u) ? 1 : 0;
    }
    __syncthreads();

    int start = blockIdx.x * 512 + tid;
    if (s_is64) {
        const long long* l64 = (const long long*)labels_raw;
        for (int i = start; i < BN; i += 512 * 16) g_labels[i] = (int)l64[i];
    } else {
        const int* l32 = (const int*)labels_raw;
        for (int i = start; i < BN; i += 512 * 16) g_labels[i] = l32[i];
    }
}

__global__ __launch_bounds__(NTHREADS, 5) void row_kernel(const float* __restrict__ sim)
{
    const int row  = blockIdx.x;
    const int tid  = threadIdx.x;
    const int lane = tid & 31;
    const int warp = tid >> 5;
    const int my_label = __ldg(&g_labels[row]);

    __shared__ float4 vsm[NVEC * NTHREADS];            // 32 KB poisoned values
    __shared__ float s_mn[NWARPS], s_mx[NWARPS];
    __shared__ float s_minall, s_maxneg;
    __shared__ float s_ps[NWARPS], s_ns[NWARPS];

    const float4* __restrict__ srow4 = reinterpret_cast<const float4*>(sim + (size_t)row * BN);
    const int4*   __restrict__ lab4  = reinterpret_cast<const int4*>(g_labels);

    // ---- pass 1: 4 NON-UNROLLED chunks of (2 sim float4 + 2 label int4) ----
    // Shallow per-warp load batches keep the per-SM L1tex queue short,
    // shrinking cross-CTA completion spread while staying above the
    // bandwidth-latency product (40 warps x 8 lines in flight).
    float mn = CUDART_INF_F;    // min over all x == hardest positive (poisoned)
    float mx = -CUDART_INF_F;   // max over all x == hardest negative

    #pragma unroll 1
    for (int c = 0; c < 4; c++) {
        float4 a0 = ldcs4(srow4 + tid + (c * 2 + 0) * NTHREADS);
        float4 a1 = ldcs4(srow4 + tid + (c * 2 + 1) * NTHREADS);
        int4   b0 = __ldg(lab4 + tid + (c * 2 + 0) * NTHREADS);
        int4   b1 = __ldg(lab4 + tid + (c * 2 + 1) * NTHREADS);

        float x0 = a0.x; if (b0.x == my_label) x0 -= POISON;
        float x1 = a0.y; if (b0.y == my_label) x1 -= POISON;
        float x2 = a0.z; if (b0.z == my_label) x2 -= POISON;
        float x3 = a0.w; if (b0.w == my_label) x3 -= POISON;
        mn = fminf(fminf(mn, fminf(x0, x1)), fminf(x2, x3));
        mx = fmaxf(fmaxf(mx, fmaxf(x0, x1)), fmaxf(x2, x3));
        vsm[(c * 2 + 0) * NTHREADS + tid] = make_float4(x0, x1, x2, x3);

        float y0 = a1.x; if (b1.x == my_label) y0 -= POISON;
        float y1 = a1.y; if (b1.y == my_label) y1 -= POISON;
        float y2 = a1.z; if (b1.z == my_label) y2 -= POISON;
        float y3 = a1.w; if (b1.w == my_label) y3 -= POISON;
        mn = fminf(fminf(mn, fminf(y0, y1)), fminf(y2, y3));
        mx = fmaxf(fmaxf(mx, fmaxf(y0, y1)), fmaxf(y2, y3));
        vsm[(c * 2 + 1) * NTHREADS + tid] = make_float4(y0, y1, y2, y3);
    }
    const float my_mn = mn;                            // thread-local pos trigger

    // ---- block reduce min_all / max_neg ----
    #pragma unroll
    for (int o = 16; o; o >>= 1) {
        mn = fminf(mn, __shfl_xor_sync(0xffffffffu, mn, o));
        mx = fmaxf(mx, __shfl_xor_sync(0xffffffffu, mx, o));
    }
    if (lane == 0) { s_mn[warp] = mn; s_mx[warp] = mx; }
    __syncthreads();
    if (warp == 0) {
        float a = (lane < NWARPS) ? s_mn[lane] : CUDART_INF_F;
        float b = (lane < NWARPS) ? s_mx[lane] : -CUDART_INF_F;
        #pragma unroll
        for (int o = 4; o; o >>= 1) {
            a = fminf(a, __shfl_xor_sync(0xffffffffu, a, o));
            b = fmaxf(b, __shfl_xor_sync(0xffffffffu, b, o));
        }
        if (lane == 0) { s_minall = a; s_maxneg = b; }
    }
    __syncthreads();

    const float pb_up = __int_as_float(__float_as_int(PB) - 1);  // next float toward 0
    // Positive exists iff min_all < pb_up. Then hardest positive (poisoned) =
    // min_all, and sel_neg threshold tn = min_pos - 0.1 = min_all + 3.9.
    const float min_all = s_minall;
    const float tn = (min_all < pb_up) ? (min_all + 3.9f) : CUDART_INF_F;

    // ---- dense neg pass from smem: LDS.128 + 4x(FFMA+MUFU+FSETP+@FADD) ----
    float ns0 = 0.0f, ns1 = 0.0f, ns2 = 0.0f, ns3 = 0.0f;
    #pragma unroll
    for (int j = 0; j < NVEC; j++) {
        float4 x = vsm[j * NTHREADS + tid];
        float e0 = ex2(fmaf(x.x, K40, C40));
        float e1 = ex2(fmaf(x.y, K40, C40));
        float e2 = ex2(fmaf(x.z, K40, C40));
        float e3 = ex2(fmaf(x.w, K40, C40));
        if (x.x > tn) ns0 += e0;    // poisoned x <= -3 < tn always (tn >= -1.1)
        if (x.y > tn) ns1 += e1;
        if (x.z > tn) ns2 += e2;
        if (x.w > tn) ns3 += e3;
    }
    float neg_sum = (ns0 + ns1) + (ns2 + ns3);

    // ---- rare pos pass (this thread owns >= 1 positive) ----
    float pos_sum = 0.0f;
    if (my_mn < pb_up) {
        // sel_pos: x <= PB (positive) AND s - 0.1 < max_neg i.e. x < max_neg - 3.9
        float tp = fminf(pb_up, s_maxneg - 3.9f);
        #pragma unroll
        for (int j = 0; j < NVEC; j++) {
            float4 x = vsm[j * NTHREADS + tid];
            float e0 = ex2(fmaf(x.x, KP, CP));   // exp(-2(s-0.5)) on poisoned x
            float e1 = ex2(fmaf(x.y, KP, CP));
            float e2 = ex2(fmaf(x.z, KP, CP));
            float e3 = ex2(fmaf(x.w, KP, CP));
            if (x.x < tp) pos_sum += e0;
            if (x.y < tp) pos_sum += e1;
            if (x.z < tp) pos_sum += e2;
            if (x.w < tp) pos_sum += e3;
        }
    }

    // ---- block reduce the two sums ----
    #pragma unroll
    for (int o = 16; o; o >>= 1) {
        pos_sum += __shfl_xor_sync(0xffffffffu, pos_sum, o);
        neg_sum += __shfl_xor_sync(0xffffffffu, neg_sum, o);
    }
    if (lane == 0) { s_ps[warp] = pos_sum; s_ns[warp] = neg_sum; }
    __syncthreads();
    if (tid == 0) {
        float ps = 0.0f, ns = 0.0f;
        #pragma unroll
        for (int wi = 0; wi < NWARPS; wi++) { ps += s_ps[wi]; ns += s_ns[wi]; }
        float loss = 0.0f;
        if (ps > 0.0f && ns > 0.0f)      // exp > 0: ps>0 <=> any(sel_pos)
            loss = log1pf(ps) * 0.5f + log1pf(ns) * 0.025f;
        g_row_loss[row] = loss;
    }
}

__global__ __launch_bounds__(1024) void reduce_kernel(float* __restrict__ out) {
    int tid = threadIdx.x;
    float sum = 0.0f;
    #pragma unroll
    for (int i = 0; i < BN / 1024; i++) sum += g_row_loss[tid + i * 1024];
    __shared__ float s[32];
    #pragma unroll
    for (int o = 16; o; o >>= 1) sum += __shfl_xor_sync(0xffffffffu, sum, o);
    if ((tid & 31) == 0) s[tid >> 5] = sum;
    __syncthreads();
    if (tid < 32) {
        float x = s[tid];
        #pragma unroll
        for (int o = 16; o; o >>= 1) x += __shfl_xor_sync(0xffffffffu, x, o);
        if (tid == 0) out[0] = x / (float)BN;
    }
}

extern "C" void kernel_launch(void* const* d_in, const int* in_sizes, int n_in,
                              void* d_out, int out_size) {
    // Guard against input ordering: sim has BN*BN elements, labels BN.
    const void* p0 = d_in[0];
    const void* p1 = d_in[1];
    const float* sim;
    const void*  labels;
    if (in_sizes[0] == BN) { labels = p0; sim = (const float*)p1; }
    else                   { sim = (const float*)p0; labels = p1; }
    float* out = (float*)d_out;

    prep_labels_kernel<<<16, 512>>>(labels);
    row_kernel<<<BN, NTHREADS>>>(sim);
    reduce_kernel<<<1, 1024>>>(out);
}

// round 14
// speedup vs baseline: 1.4333x; 1.1899x over previous
#include <cuda_runtime.h>
#include <math_constants.h>

// MultiSimilarityLoss: sim_mat [8192,8192] f32, labels [8192] i64-or-i32 -> scalar f32
//
// R14 = measured-best composition from the R6/R9/R12/R13 single-variable
// decomposition:
//   * 3-kernel structure (prep -> labels; row; reduce) -- counter atomics cost +6.6us
//   * deep 2x4 front-batched sim LDG.cs.128            -- shallow chunks cost +6.6us
//   * u16 labels via uint2 + XOR half-word compare     -- saves 4.2us vs int32
//   * 256thr x 32 elems, 32 KB smem value buffer, 5 CTAs/SM
//
//  - Poison: same-labeled elements x = s - 4 (in [-5,-3]).
//    * min over ALL x == hardest positive (self always poisoned, negs >= -1).
//    * max over ALL x == hardest negative (poison can't win).
//  - u16 compare: q = pair ^ (ml|ml<<16); even elem same iff (q&0xFFFF)==0,
//    odd elem same iff q < 0x10000.
//  - Dense pass2: LDS.128 + 4x(FFMA + MUFU.EX2 + FSETP + @FADD).
//  - Pos-side exp in a rare branch (~1.5% of threads).

constexpr int BN        = 8192;
constexpr int NTHREADS  = 256;
constexpr int PER       = BN / NTHREADS;   // 32
constexpr int NVEC      = PER / 4;         // 8 float4 slots per thread
constexpr int NWARPS    = NTHREADS / 32;   // 8

constexpr float ONE_MEPS = 1.0f - 1e-5f;          // pos threshold on s
constexpr float POISON   = 4.0f;
constexpr float PB       = ONE_MEPS - POISON;     // poisoned pos boundary ~ -3.00001
// exp(40(s-0.5)) = exp2(x*K40 + C40)
constexpr float K40 = 57.706801635558536f;        //  40*log2(e)
constexpr float C40 = -28.853400817779268f;       // -20*log2(e)
// exp(-2(s-0.5)) with s = x+4  ->  exp2(x*KP + CP)
constexpr float KP  = -2.885390081777927f;        //  -2*log2(e)
constexpr float CP  = -10.098865286222744f;       //  -7*log2(e)

__device__ unsigned short g_labels16[BN];
__device__ float g_row_loss[BN];

__device__ __forceinline__ float ex2(float a) {
    float r;
    asm("ex2.approx.ftz.f32 %0, %1;" : "=f"(r) : "f"(a));
    return r;
}

// Streaming (evict-first) 128-bit load: touched exactly once.
__device__ __forceinline__ float4 ldcs4(const float4* p) {
    float4 r;
    asm("ld.global.cs.v4.f32 {%0,%1,%2,%3}, [%4];"
        : "=f"(r.x), "=f"(r.y), "=f"(r.z), "=f"(r.w) : "l"(p));
    return r;
}

// Dtype detection: odd 32-bit words are high halves (all zero, labels<1024) iff
// int64. 32 sampled words: P(false positive for int32) = (1/1024)^32 ~ 0.
__global__ __launch_bounds__(512) void prep_labels_kernel(const void* __restrict__ labels_raw) {
    const int tid = threadIdx.x;
    const unsigned* w = (const unsigned*)labels_raw;

    __shared__ int s_is64;
    if (tid < 32) {
        unsigned f = w[2 * tid + 1];
        unsigned any = __ballot_sync(0xffffffffu, f != 0u);
        if (tid == 0) s_is64 = (any == 0u) ? 1 : 0;
    }
    __syncthreads();

    int start = blockIdx.x * 512 + tid;
    if (s_is64) {
        const long long* l64 = (const long long*)labels_raw;
        for (int i = start; i < BN; i += 512 * 16) g_labels16[i] = (unsigned short)l64[i];
    } else {
        const int* l32 = (const int*)labels_raw;
        for (int i = start; i < BN; i += 512 * 16) g_labels16[i] = (unsigned short)l32[i];
    }
}

__global__ __launch_bounds__(NTHREADS, 5) void row_kernel(const float* __restrict__ sim)
{
    const int row  = blockIdx.x;
    const int tid  = threadIdx.x;
    const int lane = tid & 31;
    const int warp = tid >> 5;

    const unsigned ml  = (unsigned)__ldg(&g_labels16[row]);
    const unsigned pat = ml * 0x00010001u;             // ml in both u16 halves

    __shared__ float4 vsm[NVEC * NTHREADS];            // 32 KB poisoned values
    __shared__ float s_mn[NWARPS], s_mx[NWARPS];
    __shared__ float s_minall, s_maxneg;
    __shared__ float s_ps[NWARPS], s_ns[NWARPS];

    const float4* __restrict__ srow4 = reinterpret_cast<const float4*>(sim + (size_t)row * BN);
    const uint2*  __restrict__ labu  = reinterpret_cast<const uint2*>(g_labels16);
    // uint2 slot j4 covers labels/cols 4*j4 .. 4*j4+3, matching float4 slot j4.

    // ---- pass 1: 2 chunks of (4 sim float4 + 4 label uint2) front-batched ----
    float mn = CUDART_INF_F;    // min over all x == hardest positive (poisoned)
    float mx = -CUDART_INF_F;   // max over all x == hardest negative

    #pragma unroll
    for (int c = 0; c < 2; c++) {
        float4 a[4];
        uint2  b[4];
        #pragma unroll
        for (int k = 0; k < 4; k++) a[k] = ldcs4(srow4 + tid + (c * 4 + k) * NTHREADS);
        #pragma unroll
        for (int k = 0; k < 4; k++) b[k] = __ldg(labu + tid + (c * 4 + k) * NTHREADS);
        #pragma unroll
        for (int k = 0; k < 4; k++) {
            unsigned q0 = b[k].x ^ pat;
            unsigned q1 = b[k].y ^ pat;
            float x0 = a[k].x; if ((q0 & 0xFFFFu) == 0u) x0 -= POISON;  // even: low half
            float x1 = a[k].y; if (q0 < 0x10000u)        x1 -= POISON;  // odd: high half
            float x2 = a[k].z; if ((q1 & 0xFFFFu) == 0u) x2 -= POISON;
            float x3 = a[k].w; if (q1 < 0x10000u)        x3 -= POISON;
            mn = fminf(fminf(mn, fminf(x0, x1)), fminf(x2, x3));
            mx = fmaxf(fmaxf(mx, fmaxf(x0, x1)), fmaxf(x2, x3));
            vsm[(c * 4 + k) * NTHREADS + tid] = make_float4(x0, x1, x2, x3);
        }
    }
    const float my_mn = mn;                            // thread-local pos trigger

    // ---- block reduce min_all / max_neg ----
    #pragma unroll
    for (int o = 16; o; o >>= 1) {
        mn = fminf(mn, __shfl_xor_sync(0xffffffffu, mn, o));
        mx = fmaxf(mx, __shfl_xor_sync(0xffffffffu, mx, o));
    }
    if (lane == 0) { s_mn[warp] = mn; s_mx[warp] = mx; }
    __syncthreads();
    if (warp == 0) {
        float a = (lane < NWARPS) ? s_mn[lane] : CUDART_INF_F;
        float b = (lane < NWARPS) ? s_mx[lane] : -CUDART_INF_F;
        #pragma unroll
        for (int o = 4; o; o >>= 1) {
            a = fminf(a, __shfl_xor_sync(0xffffffffu, a, o));
            b = fmaxf(b, __shfl_xor_sync(0xffffffffu, b, o));
        }
        if (lane == 0) { s_minall = a; s_maxneg = b; }
    }
    __syncthreads();

    const float pb_up = __int_as_float(__float_as_int(PB) - 1);  // next float toward 0
    // Positive exists iff min_all < pb_up. Then hardest positive (poisoned) =
    // min_all, and sel_neg threshold tn = min_pos - 0.1 = min_all + 3.9.
    const float min_all = s_minall;
    const float tn = (min_all < pb_up) ? (min_all + 3.9f) : CUDART_INF_F;

    // ---- dense neg pass from smem: LDS.128 + 4x(FFMA+MUFU+FSETP+@FADD) ----
    float ns0 = 0.0f, ns1 = 0.0f, ns2 = 0.0f, ns3 = 0.0f;
    #pragma unroll
    for (int j = 0; j < NVEC; j++) {
        float4 x = vsm[j * NTHREADS + tid];
        float e0 = ex2(fmaf(x.x, K40, C40));
        float e1 = ex2(fmaf(x.y, K40, C40));
        float e2 = ex2(fmaf(x.z, K40, C40));
        float e3 = ex2(fmaf(x.w, K40, C40));
        if (x.x > tn) ns0 += e0;    // poisoned x <= -3 < tn always (tn >= -1.1)
        if (x.y > tn) ns1 += e1;
        if (x.z > tn) ns2 += e2;
        if (x.w > tn) ns3 += e3;
    }
    float neg_sum = (ns0 + ns1) + (ns2 + ns3);

    // ---- rare pos pass (this thread owns >= 1 positive) ----
    float pos_sum = 0.0f;
    if (my_mn < pb_up) {
        // sel_pos: x <= PB (positive) AND s - 0.1 < max_neg i.e. x < max_neg - 3.9
        float tp = fminf(pb_up, s_maxneg - 3.9f);
        #pragma unroll
        for (int j = 0; j < NVEC; j++) {
            float4 x = vsm[j * NTHREADS + tid];
            float e0 = ex2(fmaf(x.x, KP, CP));   // exp(-2(s-0.5)) on poisoned x
            float e1 = ex2(fmaf(x.y, KP, CP));
            float e2 = ex2(fmaf(x.z, KP, CP));
            float e3 = ex2(fmaf(x.w, KP, CP));
            if (x.x < tp) pos_sum += e0;
            if (x.y < tp) pos_sum += e1;
            if (x.z < tp) pos_sum += e2;
            if (x.w < tp) pos_sum += e3;
        }
    }

    // ---- block reduce the two sums ----
    #pragma unroll
    for (int o = 16; o; o >>= 1) {
        pos_sum += __shfl_xor_sync(0xffffffffu, pos_sum, o);
        neg_sum += __shfl_xor_sync(0xffffffffu, neg_sum, o);
    }
    if (lane == 0) { s_ps[warp] = pos_sum; s_ns[warp] = neg_sum; }
    __syncthreads();
    if (tid == 0) {
        float ps = 0.0f, ns = 0.0f;
        #pragma unroll
        for (int wi = 0; wi < NWARPS; wi++) { ps += s_ps[wi]; ns += s_ns[wi]; }
        float loss = 0.0f;
        if (ps > 0.0f && ns > 0.0f)      // exp > 0: ps>0 <=> any(sel_pos)
            loss = log1pf(ps) * 0.5f + log1pf(ns) * 0.025f;
        g_row_loss[row] = loss;
    }
}

__global__ __launch_bounds__(1024) void reduce_kernel(float* __restrict__ out) {
    int tid = threadIdx.x;
    float sum = 0.0f;
    #pragma unroll
    for (int i = 0; i < BN / 1024; i++) sum += g_row_loss[tid + i * 1024];
    __shared__ float s[32];
    #pragma unroll
    for (int o = 16; o; o >>= 1) sum += __shfl_xor_sync(0xffffffffu, sum, o);
    if ((tid & 31) == 0) s[tid >> 5] = sum;
    __syncthreads();
    if (tid < 32) {
        float x = s[tid];
        #pragma unroll
        for (int o = 16; o; o >>= 1) x += __shfl_xor_sync(0xffffffffu, x, o);
        if (tid == 0) out[0] = x / (float)BN;
    }
}

extern "C" void kernel_launch(void* const* d_in, const int* in_sizes, int n_in,
                              void* d_out, int out_size) {
    // Guard against input ordering: sim has BN*BN elements, labels BN.
    const void* p0 = d_in[0];
    const void* p1 = d_in[1];
    const float* sim;
    const void*  labels;
    if (in_sizes[0] == BN) { labels = p0; sim = (const float*)p1; }
    else                   { sim = (const float*)p0; labels = p1; }
    float* out = (float*)d_out;

    prep_labels_kernel<<<16, 512>>>(labels);
    row_kernel<<<BN, NTHREADS>>>(sim);
    reduce_kernel<<<1, 1024>>>(out);
}